// round 1
// baseline (speedup 1.0000x reference)
#include <cuda_runtime.h>
#include <cuda_bf16.h>

typedef unsigned long long ull;

// ---- f32x2 packed helpers (Blackwell sm_100a+) ----
__device__ __forceinline__ ull ffma2(ull a, ull b, ull c) {
    ull d;
    asm("fma.rn.f32x2 %0, %1, %2, %3;" : "=l"(d) : "l"(a), "l"(b), "l"(c));
    return d;
}
__device__ __forceinline__ ull pack2(float lo, float hi) {
    ull r;
    asm("mov.b64 %0, {%1, %2};" : "=l"(r) : "f"(lo), "f"(hi));
    return r;
}
__device__ __forceinline__ void unpack2(ull v, float& lo, float& hi) {
    asm("mov.b64 {%0, %1}, %2;" : "=f"(lo), "=f"(hi) : "l"(v));
}

// SMEM layout (floats)
//   XS : [256][66]  combined inputs (col0 = q_out, cols 1..63 = x_c)   16896
//   W1 : [32][64]                                                       2048
//   W2 : [16][32]                                                        512
//   W3 : [16]                                                             16
//   B1 : [32]                                                             32
//   B2 : [16]                                                             16
static constexpr int TILE = 256;
static constexpr int XS_STRIDE = 66;             // even -> 8B-aligned ull reads
static constexpr int OFF_XS = 0;
static constexpr int OFF_W1 = TILE * XS_STRIDE;  // 16896
static constexpr int OFF_W2 = OFF_W1 + 32 * 64;  // 18944
static constexpr int OFF_W3 = OFF_W2 + 16 * 32;  // 19456
static constexpr int OFF_B1 = OFF_W3 + 16;       // 19472
static constexpr int OFF_B2 = OFF_B1 + 32;       // 19504
static constexpr int SMEM_FLOATS = OFF_B2 + 16;  // 19520
static constexpr int SMEM_BYTES = SMEM_FLOATS * 4;  // 78080

__global__ void __launch_bounds__(256, 2)
hybridq_kernel(const float* __restrict__ x_q,
               const float* __restrict__ x_c,
               const float* __restrict__ q_params,
               const float* __restrict__ w1,
               const float* __restrict__ b1,
               const float* __restrict__ w2,
               const float* __restrict__ b2,
               const float* __restrict__ w3,
               const float* __restrict__ b3,
               float* __restrict__ out,
               int B)
{
    extern __shared__ float sm[];
    float* XS = sm + OFF_XS;
    float* W1 = sm + OFF_W1;
    float* W2 = sm + OFF_W2;
    float* W3 = sm + OFF_W3;
    float* B1 = sm + OFF_B1;
    float* B2 = sm + OFF_B2;

    const int tid = threadIdx.x;
    const int r0  = blockIdx.x * TILE;
    const int rows = min(TILE, B - r0);

    // ---- stage weights (coalesced, layouts identical to gmem) ----
    #pragma unroll
    for (int i = 0; i < 8; ++i) W1[tid + 256 * i] = w1[tid + 256 * i];
    #pragma unroll
    for (int i = 0; i < 2; ++i) W2[tid + 256 * i] = w2[tid + 256 * i];
    if (tid < 16) W3[tid] = w3[tid];
    if (tid < 32) B1[tid] = b1[tid];
    if (tid < 16) B2[tid] = b2[tid];

    // ---- q_out for this thread's row (closed-form circuit) ----
    const float qp1 = __ldg(q_params + 1);
    const float qp2 = __ldg(q_params + 2);
    if (tid < rows) {
        const long long g = (long long)(r0 + tid) * 3;
        float t1 = x_q[g + 1] + qp1;
        float t2 = x_q[g + 2] + qp2;
        XS[tid * XS_STRIDE] = __cosf(t1) * __cosf(t2);
    }

    // ---- stage x_c tile: contiguous gmem region, scatter into [row][1+c] ----
    {
        const float* src = x_c + (long long)r0 * 63;
        const int lim = rows * 63;
        #pragma unroll
        for (int i = 0; i < 63; ++i) {
            int idx = tid + 256 * i;
            if (idx < lim) {
                int row = idx / 63;
                int col = idx - row * 63;
                XS[row * XS_STRIDE + 1 + col] = src[idx];
            }
        }
    }
    __syncthreads();

    if (tid >= rows) return;

    const ull* xrow = reinterpret_cast<const ull*>(XS + tid * XS_STRIDE); // 32 k-pairs

    // ---- layer 1: h1[32] = relu(W1 @ combined + b1), split into 2 halves of 16 ----
    float h1v[32];
    #pragma unroll
    for (int h = 0; h < 2; ++h) {
        ull acc[16];
        #pragma unroll
        for (int t = 0; t < 16; ++t) acc[t] = pack2(B1[16 * h + t], 0.0f);
        #pragma unroll
        for (int kp = 0; kp < 32; ++kp) {
            const ull xv = xrow[kp];
            #pragma unroll
            for (int t = 0; t < 16; ++t) {
                const ull wv = *reinterpret_cast<const ull*>(&W1[(16 * h + t) * 64 + 2 * kp]);
                acc[t] = ffma2(wv, xv, acc[t]);
            }
        }
        #pragma unroll
        for (int t = 0; t < 16; ++t) {
            float lo, hi;
            unpack2(acc[t], lo, hi);
            h1v[16 * h + t] = fmaxf(lo + hi, 0.0f);
        }
    }

    // ---- layer 2: h2[16] = relu(W2 @ h1 + b2), j-paired f32x2 ----
    ull hp[16];
    #pragma unroll
    for (int u = 0; u < 16; ++u) hp[u] = pack2(h1v[2 * u], h1v[2 * u + 1]);

    float h2v[16];
    #pragma unroll
    for (int m = 0; m < 16; ++m) {
        ull a2 = pack2(B2[m], 0.0f);
        #pragma unroll
        for (int u = 0; u < 16; ++u) {
            const ull wv = *reinterpret_cast<const ull*>(&W2[m * 32 + 2 * u]);
            a2 = ffma2(wv, hp[u], a2);
        }
        float lo, hi;
        unpack2(a2, lo, hi);
        h2v[m] = fmaxf(lo + hi, 0.0f);
    }

    // ---- layer 3: out = w3 . h2 + b3 ----
    ull a3 = pack2(__ldg(b3), 0.0f);
    #pragma unroll
    for (int v = 0; v < 8; ++v) {
        const ull wv = *reinterpret_cast<const ull*>(&W3[2 * v]);
        a3 = ffma2(wv, pack2(h2v[2 * v], h2v[2 * v + 1]), a3);
    }
    float lo, hi;
    unpack2(a3, lo, hi);
    out[r0 + tid] = lo + hi;
}

extern "C" void kernel_launch(void* const* d_in, const int* in_sizes, int n_in,
                              void* d_out, int out_size)
{
    const float* x_q      = (const float*)d_in[0];
    const float* x_c      = (const float*)d_in[1];
    const float* q_params = (const float*)d_in[2];
    const float* w1       = (const float*)d_in[3];
    const float* b1       = (const float*)d_in[4];
    const float* w2       = (const float*)d_in[5];
    const float* b2       = (const float*)d_in[6];
    const float* w3       = (const float*)d_in[7];
    const float* b3       = (const float*)d_in[8];
    float* out            = (float*)d_out;

    const int B = in_sizes[0] / 3;
    const int blocks = (B + TILE - 1) / TILE;

    cudaFuncSetAttribute(hybridq_kernel,
                         cudaFuncAttributeMaxDynamicSharedMemorySize, SMEM_BYTES);

    hybridq_kernel<<<blocks, 256, SMEM_BYTES>>>(
        x_q, x_c, q_params, w1, b1, w2, b2, w3, b3, out, B);
}

// round 2
// speedup vs baseline: 1.2542x; 1.2542x over previous
#include <cuda_runtime.h>

typedef unsigned long long ull;

// ---- f32x2 packed helpers (Blackwell) ----
__device__ __forceinline__ ull ffma2(ull a, ull b, ull c) {
    ull d;
    asm("fma.rn.f32x2 %0, %1, %2, %3;" : "=l"(d) : "l"(a), "l"(b), "l"(c));
    return d;
}
__device__ __forceinline__ ull pack2(float lo, float hi) {
    ull r;
    asm("mov.b64 %0, {%1, %2};" : "=l"(r) : "f"(lo), "f"(hi));
    return r;
}
__device__ __forceinline__ void unpack2(ull v, float& lo, float& hi) {
    asm("mov.b64 {%0, %1}, %2;" : "=f"(lo), "=f"(hi) : "l"(v));
}

static constexpr int THREADS = 256;
static constexpr int R = 3;                 // rows per thread
static constexpr int TILE = THREADS * R;    // 768 rows per CTA

// SMEM layout (float offsets)
static constexpr int W1_STRIDE = 34;        // WT1[k][t], k=0..63, t=0..31 (pad->8B align, 2-way write conflict only)
static constexpr int W2_STRIDE = 18;        // WT2[j][m], j=0..31, m=0..15
static constexpr int OFF_XS  = 0;                       // x_c verbatim: TILE*63 = 48384
static constexpr int OFF_Q   = OFF_XS + TILE * 63;      // 48384 : q_out column, TILE floats
static constexpr int OFF_WT1 = OFF_Q + TILE;            // 49152 : 64*34 = 2176
static constexpr int OFF_WT2 = OFF_WT1 + 64 * W1_STRIDE;// 51328 : 32*18 = 576
static constexpr int OFF_W3  = OFF_WT2 + 32 * W2_STRIDE;// 51904 : 16
static constexpr int OFF_B1  = OFF_W3 + 16;             // 51920 : 32
static constexpr int OFF_B2  = OFF_B1 + 32;             // 51952 : 16
static constexpr int SMEM_FLOATS = OFF_B2 + 16;         // 51968
static constexpr int SMEM_BYTES  = SMEM_FLOATS * 4;     // 207872

__global__ void __launch_bounds__(THREADS, 1)
hybridq_kernel(const float* __restrict__ x_q,
               const float* __restrict__ x_c,
               const float* __restrict__ q_params,
               const float* __restrict__ w1,
               const float* __restrict__ b1,
               const float* __restrict__ w2,
               const float* __restrict__ b2,
               const float* __restrict__ w3,
               const float* __restrict__ b3,
               float* __restrict__ out,
               int B)
{
    extern __shared__ float sm[];
    float* XS  = sm + OFF_XS;
    float* Q   = sm + OFF_Q;
    float* WT1 = sm + OFF_WT1;
    float* WT2 = sm + OFF_WT2;
    float* W3S = sm + OFF_W3;
    float* B1S = sm + OFF_B1;
    float* B2S = sm + OFF_B2;

    const int tid = threadIdx.x;
    const int r0  = blockIdx.x * TILE;
    const int rows = min(TILE, B - r0);

    // ---- stage weights (transposed so output-pairs are contiguous) ----
    #pragma unroll
    for (int i = 0; i < 8; ++i) {
        int idx = tid + 256 * i;                // w1 is [32][64]
        int t = idx >> 6, k = idx & 63;
        WT1[k * W1_STRIDE + t] = w1[idx];
    }
    #pragma unroll
    for (int i = 0; i < 2; ++i) {
        int idx = tid + 256 * i;                // w2 is [16][32]
        int m = idx >> 5, j = idx & 31;
        WT2[j * W2_STRIDE + m] = w2[idx];
    }
    if (tid < 16) W3S[tid] = w3[tid];
    if (tid < 32) B1S[tid] = b1[tid];
    if (tid < 16) B2S[tid] = b2[tid];

    // ---- q_out column (closed-form circuit: cos(x1+w1)*cos(x2+w2)) ----
    {
        const float qp1 = __ldg(q_params + 1);
        const float qp2 = __ldg(q_params + 2);
        #pragma unroll
        for (int r = 0; r < R; ++r) {
            int row = tid + 256 * r;
            if (row < rows) {
                long long g = (long long)(r0 + row) * 3;
                Q[row] = __cosf(x_q[g + 1] + qp1) * __cosf(x_q[g + 2] + qp2);
            }
        }
    }

    // ---- stage x_c verbatim (pure coalesced copy, no scatter) ----
    {
        const float4* src = reinterpret_cast<const float4*>(x_c + (long long)r0 * 63);
        float4* dst = reinterpret_cast<float4*>(XS);
        const int n = rows * 63;
        const int n4 = n >> 2;
        for (int i = tid; i < n4; i += THREADS) dst[i] = src[i];
        const int base = n4 << 2;
        if (tid < (n & 3)) XS[base + tid] = x_c[(long long)r0 * 63 + base + tid];
    }
    __syncthreads();

    // row base offsets into XS (lane stride 63 -> conflict-free)
    int xb[R];
    #pragma unroll
    for (int r = 0; r < R; ++r) xb[r] = (tid + 256 * r) * 63;

    // ================= layer 1: h1[32] = relu(W1 @ x + b1) =================
    // acc[r][p] holds outputs (2p, 2p+1) in the two f32 lanes.
    ull acc[R][16];
    #pragma unroll
    for (int p = 0; p < 16; ++p) {
        const ull bp = *reinterpret_cast<const ull*>(B1S + 2 * p);
        #pragma unroll
        for (int r = 0; r < R; ++r) acc[r][p] = bp;
    }

    // k = 0 : q_out feature
    {
        ull xx[R];
        #pragma unroll
        for (int r = 0; r < R; ++r) {
            float q = Q[tid + 256 * r];
            xx[r] = pack2(q, q);
        }
        #pragma unroll
        for (int p = 0; p < 16; ++p) {
            const ull wv = *reinterpret_cast<const ull*>(WT1 + 2 * p);
            #pragma unroll
            for (int r = 0; r < R; ++r) acc[r][p] = ffma2(wv, xx[r], acc[r][p]);
        }
    }

    // k = 1..63 : x_c features
    #pragma unroll 7
    for (int k = 1; k < 64; ++k) {
        ull xx[R];
        #pragma unroll
        for (int r = 0; r < R; ++r) {
            float x = XS[xb[r] + (k - 1)];
            xx[r] = pack2(x, x);
        }
        const float* wrow = WT1 + k * W1_STRIDE;
        #pragma unroll
        for (int p = 0; p < 16; ++p) {
            const ull wv = *reinterpret_cast<const ull*>(wrow + 2 * p);
            #pragma unroll
            for (int r = 0; r < R; ++r) acc[r][p] = ffma2(wv, xx[r], acc[r][p]);
        }
    }

    float h1[R][32];
    #pragma unroll
    for (int r = 0; r < R; ++r)
        #pragma unroll
        for (int p = 0; p < 16; ++p) {
            float lo, hi;
            unpack2(acc[r][p], lo, hi);
            h1[r][2 * p]     = fmaxf(lo, 0.0f);
            h1[r][2 * p + 1] = fmaxf(hi, 0.0f);
        }

    // ================= layer 2: h2[16] = relu(W2 @ h1 + b2) =================
    ull a2[R][8];
    #pragma unroll
    for (int p = 0; p < 8; ++p) {
        const ull bp = *reinterpret_cast<const ull*>(B2S + 2 * p);
        #pragma unroll
        for (int r = 0; r < R; ++r) a2[r][p] = bp;
    }
    #pragma unroll
    for (int j = 0; j < 32; ++j) {
        const float* w2r = WT2 + j * W2_STRIDE;
        ull xx[R];
        #pragma unroll
        for (int r = 0; r < R; ++r) xx[r] = pack2(h1[r][j], h1[r][j]);
        #pragma unroll
        for (int p = 0; p < 8; ++p) {
            const ull wv = *reinterpret_cast<const ull*>(w2r + 2 * p);
            #pragma unroll
            for (int r = 0; r < R; ++r) a2[r][p] = ffma2(wv, xx[r], a2[r][p]);
        }
    }

    float h2[R][16];
    #pragma unroll
    for (int r = 0; r < R; ++r)
        #pragma unroll
        for (int p = 0; p < 8; ++p) {
            float lo, hi;
            unpack2(a2[r][p], lo, hi);
            h2[r][2 * p]     = fmaxf(lo, 0.0f);
            h2[r][2 * p + 1] = fmaxf(hi, 0.0f);
        }

    // ================= layer 3: out = w3 . h2 + b3 =================
    const float b3v = __ldg(b3);
    #pragma unroll
    for (int r = 0; r < R; ++r) {
        ull a3 = pack2(b3v, 0.0f);
        #pragma unroll
        for (int v = 0; v < 8; ++v) {
            const ull wv = *reinterpret_cast<const ull*>(W3S + 2 * v);
            a3 = ffma2(wv, pack2(h2[r][2 * v], h2[r][2 * v + 1]), a3);
        }
        float lo, hi;
        unpack2(a3, lo, hi);
        int row = tid + 256 * r;
        if (row < rows) out[r0 + row] = lo + hi;
    }
}

extern "C" void kernel_launch(void* const* d_in, const int* in_sizes, int n_in,
                              void* d_out, int out_size)
{
    const float* x_q      = (const float*)d_in[0];
    const float* x_c      = (const float*)d_in[1];
    const float* q_params = (const float*)d_in[2];
    const float* w1       = (const float*)d_in[3];
    const float* b1       = (const float*)d_in[4];
    const float* w2       = (const float*)d_in[5];
    const float* b2       = (const float*)d_in[6];
    const float* w3       = (const float*)d_in[7];
    const float* b3       = (const float*)d_in[8];
    float* out            = (float*)d_out;

    const int B = in_sizes[0] / 3;
    const int blocks = (B + TILE - 1) / TILE;

    cudaFuncSetAttribute(hybridq_kernel,
                         cudaFuncAttributeMaxDynamicSharedMemorySize, SMEM_BYTES);

    hybridq_kernel<<<blocks, THREADS, SMEM_BYTES>>>(
        x_q, x_c, q_params, w1, b1, w2, b2, w3, b3, out, B);
}